// round 15
// baseline (speedup 1.0000x reference)
#include <cuda_runtime.h>

// Problem constants
#define B     256
#define T     512
#define NPOS  128
#define NACT  32
#define DIN   160            // NPOS + NACT
#define H     512
#define DTOT  672            // DIN + H
#define NCTA  128            // recurrent grid size (wave-1 resident)
#define HC    4              // hidden units per CTA
#define NG    16             // gate rows per CTA = 4 * HC
#define KH0   336            // half0 k-range: x(160) + h[0:176)
#define KH0H  176            // h rows in half0
#define KH1   336            // half1 k-range: h[176:512)

// ---------------------------------------------------------------------------
// Device scratch (static — no cudaMalloc allowed)
// ---------------------------------------------------------------------------
__device__ float g_XT[(size_t)T * DIN * B];        // x transposed: [t][d][b]
__device__ float g_hall[(size_t)(T + 1) * H * B];  // h history:    [t][j][b]
__device__ unsigned int          g_count;
__device__ volatile unsigned int g_gen;

// ---------------------------------------------------------------------------
// Packed f32x2 helpers
// ---------------------------------------------------------------------------
__device__ __forceinline__ unsigned long long pack2(float lo, float hi) {
    unsigned long long r;
    asm("mov.b64 %0, {%1, %2};" : "=l"(r) : "f"(lo), "f"(hi));
    return r;
}
__device__ __forceinline__ float2 unpack2(unsigned long long v) {
    float2 r;
    asm("mov.b64 {%0, %1}, %2;" : "=f"(r.x), "=f"(r.y) : "l"(v));
    return r;
}
__device__ __forceinline__ void fma2(unsigned long long& d,
                                     unsigned long long a,
                                     unsigned long long w) {
    asm("fma.rn.f32x2 %0, %1, %2, %0;" : "+l"(d) : "l"(a), "l"(w));
}
__device__ __forceinline__ void add2(unsigned long long& d, unsigned long long a) {
    asm("add.rn.f32x2 %0, %0, %1;" : "+l"(d) : "l"(a));
}
// 8 batch values (already pair-packed) for one k
__device__ __forceinline__ ulonglong2 ldcg_v2u64(const float* p) {
    ulonglong2 v;
    asm("ld.global.cg.v2.u64 {%0,%1}, [%2];" : "=l"(v.x), "=l"(v.y) : "l"(p));
    return v;
}

__device__ __forceinline__ float sigm(float x) {
    return 1.0f / (1.0f + expf(-x));
}

// 16 FFMA2: 4 gates x 4 batch-pairs.  acc[g*4+p]
__device__ __forceinline__ void dofma16(unsigned long long* acc,
                                        ulonglong2 va, ulonglong2 vb,
                                        float4 wv) {
    unsigned long long w0 = pack2(wv.x, wv.x);
    unsigned long long w1 = pack2(wv.y, wv.y);
    unsigned long long w2 = pack2(wv.z, wv.z);
    unsigned long long w3 = pack2(wv.w, wv.w);
    fma2(acc[0],  va.x, w0); fma2(acc[1],  va.y, w0);
    fma2(acc[2],  vb.x, w0); fma2(acc[3],  vb.y, w0);
    fma2(acc[4],  va.x, w1); fma2(acc[5],  va.y, w1);
    fma2(acc[6],  vb.x, w1); fma2(acc[7],  vb.y, w1);
    fma2(acc[8],  va.x, w2); fma2(acc[9],  va.y, w2);
    fma2(acc[10], vb.x, w2); fma2(acc[11], vb.y, w2);
    fma2(acc[12], va.x, w3); fma2(acc[13], va.y, w3);
    fma2(acc[14], vb.x, w3); fma2(acc[15], vb.y, w3);
}

// ---------------------------------------------------------------------------
// Kernel 1: prep — transpose inputs, transpose h0, reset barrier state.
// ---------------------------------------------------------------------------
__global__ void prep_kernel(const float* __restrict__ obs,
                            const float* __restrict__ act,
                            const float* __restrict__ h0) {
    const int t  = blockIdx.x;
    const int tx = threadIdx.x & 31;
    const int ty = threadIdx.x >> 5;
    __shared__ float tile[32][33];

    for (int b0 = 0; b0 < B; b0 += 32) {
        for (int d0 = 0; d0 < NPOS; d0 += 32) {
            #pragma unroll
            for (int r = 0; r < 32; r += 8)
                tile[ty + r][tx] =
                    obs[((size_t)(b0 + ty + r) * T + t) * NPOS + d0 + tx];
            __syncthreads();
            #pragma unroll
            for (int r = 0; r < 32; r += 8)
                g_XT[((size_t)t * DIN + d0 + ty + r) * B + b0 + tx] =
                    tile[tx][ty + r];
            __syncthreads();
        }
        #pragma unroll
        for (int r = 0; r < 32; r += 8)
            tile[ty + r][tx] =
                act[((size_t)(b0 + ty + r) * T + t) * NACT + tx];
        __syncthreads();
        #pragma unroll
        for (int r = 0; r < 32; r += 8)
            g_XT[((size_t)t * DIN + NPOS + ty + r) * B + b0 + tx] =
                tile[tx][ty + r];
        __syncthreads();
    }

    g_hall[(size_t)t * B + threadIdx.x] = h0[(size_t)threadIdx.x * H + t];

    if (t == 0 && threadIdx.x == 0) {
        g_count = 0u;
        g_gen   = 0u;
    }
}

// ---------------------------------------------------------------------------
// Grid barrier (monotone generation). 128 CTAs, all wave-1 resident.
// ---------------------------------------------------------------------------
__device__ __forceinline__ void grid_barrier(unsigned int target) {
    __syncthreads();
    if (threadIdx.x == 0) {
        __threadfence();
        unsigned int prev = atomicAdd(&g_count, 1u);
        if (prev == NCTA - 1) {
            g_count = 0u;
            __threadfence();
            g_gen = target;           // release
        } else {
            while (g_gen < target) __nanosleep(32);
            __threadfence();          // acquire
        }
    }
    __syncthreads();
}

// ---------------------------------------------------------------------------
// Kernel 2: persistent recurrent LSTM.
// 256 threads: tid = half*128 + w*32 + l
//   half : k-split (half0: x + h[0:176), half1: h[176:512))
//   w    : hidden unit index within CTA (0..3) -> gate rows i,f,g,o of unit
//   l    : lane -> batches [8l, 8l+8)
// Per thread tile: 4 gate rows x 8 batches (R=4, BPT=8).
// Weights resident in SMEM as float4 per (k, unit): wsh[k*4+w] = {wi,wf,wg,wo}.
// ---------------------------------------------------------------------------
__global__ void __launch_bounds__(256)
lstm_rec_kernel(const float* __restrict__ Wih,
                const float* __restrict__ Whh,
                const float* __restrict__ bih,
                const float* __restrict__ bhh,
                const float* __restrict__ c0) {
    __shared__ float4             wsh[DTOT * 4];   // 43008 B
    __shared__ unsigned long long bufq[128 * 4];   //  4096 B (combine buffer)
    __shared__ float              bsh[NG];         //    64 B

    const int tid  = threadIdx.x;
    const int rest = tid & 127;
    const int half = tid >> 7;
    const int w    = rest >> 5;          // unit 0..3
    const int l    = rest & 31;          // lane -> 8 batches
    const int j0   = blockIdx.x * HC;

    // ---- one-time weight load: wf[k*16 + unit*4 + gate] = W_row(gate*H+j0+unit)[k]
    {
        float* wf = reinterpret_cast<float*>(wsh);
        for (int idx = tid; idx < DTOT * NG; idx += 256) {
            int k = idx >> 4;
            int q = idx & 15;
            int u = q >> 2;              // unit
            int g = q & 3;               // gate
            int r = g * H + j0 + u;
            wf[idx] = (k < DIN) ? Wih[(size_t)r * DIN + k]
                                : Whh[(size_t)r * H + (k - DIN)];
        }
    }
    if (tid < NG) {
        int u = tid >> 2, g = tid & 3;
        int r = g * H + j0 + u;
        bsh[tid] = bih[r] + bhh[r];
    }
    __syncthreads();

    float bias[4];
    #pragma unroll
    for (int g = 0; g < 4; ++g) bias[g] = bsh[w * 4 + g];

    float cst[8];
    if (half == 0) {
        #pragma unroll
        for (int i = 0; i < 8; ++i)
            cst[i] = c0[(size_t)(8 * l + i) * H + j0 + w];
    }

    const int boff = 8 * l;

    // ---- time loop ----
    for (int t = 0; t < T; ++t) {
        unsigned long long acc[16];
        if (half == 0) {
            #pragma unroll
            for (int g = 0; g < 4; ++g) {
                unsigned long long bb = pack2(bias[g], bias[g]);
                acc[g * 4 + 0] = bb; acc[g * 4 + 1] = bb;
                acc[g * 4 + 2] = bb; acc[g * 4 + 3] = bb;
            }
        } else {
            #pragma unroll
            for (int q = 0; q < 16; ++q) acc[q] = 0ull;
        }

        if (half == 0) {
            const float* xp = g_XT   + (size_t)t * DIN * B + boff;
            const float* hp = g_hall + (size_t)t * H   * B + boff;
            #pragma unroll 8
            for (int k = 0; k < DIN; ++k) {
                ulonglong2 v = ldcg_v2u64(xp + (size_t)k * B);
                ulonglong2 v2; v2.x = v.x; v2.y = v.y;
                // need both halves of the 8 values:
                ulonglong2 vb = ldcg_v2u64(xp + (size_t)k * B + 4);
                dofma16(acc, v2, vb, wsh[k * 4 + w]);
            }
            #pragma unroll 8
            for (int k = 0; k < KH0H; ++k) {
                ulonglong2 va = ldcg_v2u64(hp + (size_t)k * B);
                ulonglong2 vb = ldcg_v2u64(hp + (size_t)k * B + 4);
                dofma16(acc, va, vb, wsh[(DIN + k) * 4 + w]);
            }
        } else {
            const float* hp = g_hall + (size_t)t * H * B + (size_t)KH0H * B + boff;
            #pragma unroll 8
            for (int k = 0; k < KH1; ++k) {
                ulonglong2 va = ldcg_v2u64(hp + (size_t)k * B);
                ulonglong2 vb = ldcg_v2u64(hp + (size_t)k * B + 4);
                dofma16(acc, va, vb, wsh[(KH0 + k) * 4 + w]);
            }
        }

        // ---- combine halves (4 phases through 4 KB buffer) ----
        #pragma unroll
        for (int ph = 0; ph < 4; ++ph) {
            if (half == 1) {
                ulonglong2* bp = reinterpret_cast<ulonglong2*>(&bufq[rest * 4]);
                bp[0] = make_ulonglong2(acc[ph * 4 + 0], acc[ph * 4 + 1]);
                bp[1] = make_ulonglong2(acc[ph * 4 + 2], acc[ph * 4 + 3]);
            }
            __syncthreads();
            if (half == 0) {
                add2(acc[ph * 4 + 0], bufq[rest * 4 + 0]);
                add2(acc[ph * 4 + 1], bufq[rest * 4 + 1]);
                add2(acc[ph * 4 + 2], bufq[rest * 4 + 2]);
                add2(acc[ph * 4 + 3], bufq[rest * 4 + 3]);
            }
            __syncthreads();
        }

        // ---- activations + state update (half 0 only) ----
        if (half == 0) {
            float iv[8], fv[8], gv[8], ov[8];
            #pragma unroll
            for (int p = 0; p < 4; ++p) {
                float2 a;
                a = unpack2(acc[0  + p]); iv[2*p] = a.x; iv[2*p+1] = a.y;
                a = unpack2(acc[4  + p]); fv[2*p] = a.x; fv[2*p+1] = a.y;
                a = unpack2(acc[8  + p]); gv[2*p] = a.x; gv[2*p+1] = a.y;
                a = unpack2(acc[12 + p]); ov[2*p] = a.x; ov[2*p+1] = a.y;
            }
            float hh[8];
            #pragma unroll
            for (int i = 0; i < 8; ++i) {
                float i_ = sigm(iv[i]);
                float f_ = sigm(fv[i]);
                float gg = tanhf(gv[i]);
                float o_ = sigm(ov[i]);
                float c  = f_ * cst[i] + i_ * gg;
                hh[i]    = o_ * tanhf(c);
                cst[i]   = c;
            }
            float4* op = reinterpret_cast<float4*>(
                g_hall + (size_t)(t + 1) * H * B + (size_t)(j0 + w) * B + boff);
            op[0] = make_float4(hh[0], hh[1], hh[2], hh[3]);
            op[1] = make_float4(hh[4], hh[5], hh[6], hh[7]);
        }

        grid_barrier((unsigned int)(t + 1));
    }
}

// ---------------------------------------------------------------------------
// Kernel 3: y[b][t] = h_{t+1} . W_out + b_out  (fully parallel, deterministic)
// ---------------------------------------------------------------------------
__global__ void yfinal_kernel(const float* __restrict__ wout,
                              const float* __restrict__ bout,
                              float* __restrict__ y) {
    __shared__ float ws[H];
    const int t = blockIdx.x;
    const int b = threadIdx.x;
    for (int j = threadIdx.x; j < H; j += 256) ws[j] = wout[j];
    __syncthreads();

    float s = bout[0];
    const float* hp = g_hall + (size_t)(t + 1) * H * B + b;
    #pragma unroll 8
    for (int j = 0; j < H; ++j)
        s += hp[(size_t)j * B] * ws[j];
    y[(size_t)b * T + t] = s;
}

// ---------------------------------------------------------------------------
// Launch
// ---------------------------------------------------------------------------
extern "C" void kernel_launch(void* const* d_in, const int* in_sizes, int n_in,
                              void* d_out, int out_size) {
    const float* obs  = (const float*)d_in[0];
    const float* act  = (const float*)d_in[1];
    const float* Wih  = (const float*)d_in[2];
    const float* Whh  = (const float*)d_in[3];
    const float* bih  = (const float*)d_in[4];
    const float* bhh  = (const float*)d_in[5];
    const float* Wout = (const float*)d_in[6];
    const float* bout = (const float*)d_in[7];
    const float* h0   = (const float*)d_in[8];
    const float* c0   = (const float*)d_in[9];
    float* y = (float*)d_out;

    prep_kernel<<<T, 256>>>(obs, act, h0);
    lstm_rec_kernel<<<NCTA, 256>>>(Wih, Whh, bih, bhh, c0);
    yfinal_kernel<<<T, 256>>>(Wout, bout, y);
}